// round 2
// baseline (speedup 1.0000x reference)
#include <cuda_runtime.h>
#include <math.h>

#define BB   8
#define NN   40000
#define DD   256
#define SS   128
#define HID  64

// ---------------- device scratch (no allocations allowed) ----------------
__device__ long long g_isum[BB * SS * 3];   // fixed-point coordinate sums (scale 2^32)
__device__ int       g_icnt[BB * SS];       // exact counts
__device__ float     g_h1  [BB * SS * HID]; // gelu(rel@W1+b1)
__device__ float     g_h2  [BB * SS * DD];  // h1@W2+b2
__device__ float     g_a3  [BB * SS * DD];  // h2@W3+b3
__device__ float     g_y   [BB * SS * DD];  // gelu(layernorm(a3))
__device__ float     g_a4  [BB * SS * DD];  // final per-superpoint table (masked)
__device__ float     g_mask[BB * SS];       // vmask * enough

__device__ __forceinline__ float geluf(float x) { return x * normcdff(x); }

// ---------------- K0: zero the integer accumulators ----------------
__global__ void zero_kernel() {
    int i = blockIdx.x * blockDim.x + threadIdx.x;
    if (i < BB * SS)     g_icnt[i] = 0;
    if (i < BB * SS * 3) g_isum[i] = 0;
}

// ---------------- K1: segment accumulation (shared-privatized, integer atomics) ----------------
#define PTS_PER_BLK 2048
__global__ void accum_kernel(const float* __restrict__ coords,
                             const int* __restrict__ labels) {
    __shared__ int       s_cnt[SS];
    __shared__ long long s_sum[SS * 3];
    int b    = blockIdx.y;
    int base = blockIdx.x * PTS_PER_BLK;

    for (int i = threadIdx.x; i < SS; i += blockDim.x) {
        s_cnt[i] = 0;
        s_sum[i * 3 + 0] = 0; s_sum[i * 3 + 1] = 0; s_sum[i * 3 + 2] = 0;
    }
    __syncthreads();

    const double SCALE = 4294967296.0; // 2^32 fixed point -> deterministic & (near) exact
    for (int i = threadIdx.x; i < PTS_PER_BLK; i += blockDim.x) {
        int n = base + i;
        if (n < NN) {
            long long pt = (long long)b * NN + n;
            int lab = labels[pt] & (SS - 1);   // mask keeps any dtype surprise in-bounds
            const float* c = coords + pt * 3;
            atomicAdd(&s_cnt[lab], 1);
            atomicAdd((unsigned long long*)&s_sum[lab * 3 + 0],
                      (unsigned long long)llrint((double)c[0] * SCALE));
            atomicAdd((unsigned long long*)&s_sum[lab * 3 + 1],
                      (unsigned long long)llrint((double)c[1] * SCALE));
            atomicAdd((unsigned long long*)&s_sum[lab * 3 + 2],
                      (unsigned long long)llrint((double)c[2] * SCALE));
        }
    }
    __syncthreads();

    for (int i = threadIdx.x; i < SS; i += blockDim.x) {
        if (s_cnt[i]) {
            atomicAdd(&g_icnt[b * SS + i], s_cnt[i]);
            atomicAdd((unsigned long long*)&g_isum[(b * SS + i) * 3 + 0],
                      (unsigned long long)s_sum[i * 3 + 0]);
            atomicAdd((unsigned long long*)&g_isum[(b * SS + i) * 3 + 1],
                      (unsigned long long)s_sum[i * 3 + 1]);
            atomicAdd((unsigned long long*)&g_isum[(b * SS + i) * 3 + 2],
                      (unsigned long long)s_sum[i * 3 + 2]);
        }
    }
}

// ---------------- K2: per-batch relative features + first tiny GEMM (rel@W1 -> gelu) ----------------
__global__ void relh1_kernel(const float* __restrict__ W1, const float* __restrict__ b1) {
    int b = blockIdx.x;
    int s = threadIdx.x; // 0..127
    __shared__ float cx[SS], cy[SS], cz[SS], vm[SS];
    __shared__ float s_nv;

    int   cnt  = g_icnt[b * SS + s];
    float cntf = (float)cnt;
    float dc   = fmaxf(cntf, 1.0f);
    const double INV = 1.0 / 4294967296.0;
    cx[s] = (float)((double)g_isum[(b * SS + s) * 3 + 0] * INV) / dc;
    cy[s] = (float)((double)g_isum[(b * SS + s) * 3 + 1] * INV) / dc;
    cz[s] = (float)((double)g_isum[(b * SS + s) * 3 + 2] * INV) / dc;
    vm[s] = (cntf >= 2.0f) ? 1.0f : 0.0f;
    __syncthreads();

    if (s == 0) {
        float t = 0.f;
        for (int i = 0; i < SS; i++) t += vm[i];
        s_nv = t;
    }
    __syncthreads();
    float nv = s_nv;

    float xs = cx[s], ys = cy[s], zs = cz[s];
    float msum = 0.f, mind = INFINITY, fcnt = 0.f;
    #pragma unroll 4
    for (int t = 0; t < SS; t++) {
        float dx = xs - cx[t], dy = ys - cy[t], dz = zs - cz[t];
        float d2 = dx * dx + dy * dy + dz * dz;
        float dist = (d2 > 0.f) ? sqrtf(d2) : 0.f;
        float v = vm[t];
        msum += dist * v;
        if (v > 0.f) mind = fminf(mind, dist);
        fcnt += (zs > cz[t] ? 1.0f : 0.0f) * v;
    }
    float denom = fmaxf(nv, 1.0f);
    float r0 = msum / denom;
    float r1 = mind;
    float r2 = zs;
    float r3 = fcnt / denom;

    // h1 = gelu(rel @ W1 + b1), W1 is [4][64]
    float* out = g_h1 + ((long long)b * SS + s) * HID;
    #pragma unroll 8
    for (int j = 0; j < HID; j++) {
        float a = b1[j]
                + r0 * W1[0 * HID + j]
                + r1 * W1[1 * HID + j]
                + r2 * W1[2 * HID + j]
                + r3 * W1[3 * HID + j];
        out[j] = geluf(a);
    }
    g_mask[b * SS + s] = vm[s] * ((nv >= 2.0f) ? 1.0f : 0.0f);
}

// ---------------- generic [128,K] @ [K,256] GEMM, 32-column chunk per block ----------------
// SEL=0: g_h1@W2 -> g_h2 ; SEL=1: g_h2@W3 -> g_a3 ; SEL=2: g_y@W4*mask -> g_a4
template <int K, int SEL>
__global__ void gemm_kernel(const float* __restrict__ W, const float* __restrict__ bias) {
    const float* X = (SEL == 0) ? g_h1 : (SEL == 1) ? g_h2 : g_y;
    float*       Y = (SEL == 0) ? g_h2 : (SEL == 1) ? g_a3 : g_a4;

    int b  = blockIdx.y;
    int c0 = blockIdx.x * 32;
    const float* Xb = X + (long long)b * SS * K;
    float*       Yb = Y + (long long)b * SS * DD;

    __shared__ float Xs[SS * 68];   // 64-wide k-tile, +4 pad
    __shared__ float Ws[64 * 32];

    int tx = threadIdx.x & 31;
    int ty = threadIdx.x >> 5;      // 0..7

    float acc[16];
    #pragma unroll
    for (int i = 0; i < 16; i++) acc[i] = 0.f;

    for (int k0 = 0; k0 < K; k0 += 64) {
        __syncthreads();
        #pragma unroll
        for (int i = threadIdx.x; i < SS * 16; i += 256) {
            int r = i >> 4, q = i & 15;
            *(float4*)(Xs + r * 68 + q * 4) = *(const float4*)(Xb + r * K + k0 + q * 4);
        }
        #pragma unroll
        for (int i = threadIdx.x; i < 64 * 32; i += 256) {
            int kk = i >> 5, c = i & 31;
            Ws[i] = W[(k0 + kk) * DD + c0 + c];
        }
        __syncthreads();
        #pragma unroll 8
        for (int kk = 0; kk < 64; kk++) {
            float w = Ws[kk * 32 + tx];
            #pragma unroll
            for (int i = 0; i < 16; i++)
                acc[i] += Xs[(ty + i * 8) * 68 + kk] * w;
        }
    }

    float bv = bias[c0 + tx];
    #pragma unroll
    for (int i = 0; i < 16; i++) {
        int r = ty + i * 8;
        float v = acc[i] + bv;
        if (SEL == 2) v *= g_mask[b * SS + r];
        Yb[r * DD + c0 + tx] = v;
    }
}

// ---------------- K5: per-row layernorm + gelu ----------------
__device__ __forceinline__ float blockSum256(float v, float* sh) {
    int lane = threadIdx.x & 31, w = threadIdx.x >> 5;
    #pragma unroll
    for (int o = 16; o > 0; o >>= 1) v += __shfl_xor_sync(0xffffffffu, v, o);
    if (lane == 0) sh[w] = v;
    __syncthreads();
    if (w == 0) {
        float t = (lane < 8) ? sh[lane] : 0.f;
        #pragma unroll
        for (int o = 4; o > 0; o >>= 1) t += __shfl_xor_sync(0xffffffffu, t, o);
        if (lane == 0) sh[0] = t;
    }
    __syncthreads();
    float r = sh[0];
    __syncthreads();
    return r;
}

__global__ void ln_gelu_kernel(const float* __restrict__ lng, const float* __restrict__ lnb) {
    __shared__ float sh[8];
    int row = blockIdx.x;          // 0 .. BB*SS-1
    int t   = threadIdx.x;         // 0 .. 255
    float x  = g_a3[(long long)row * DD + t];
    float mu = blockSum256(x, sh) * (1.0f / DD);
    float d  = x - mu;
    float var = blockSum256(d * d, sh) * (1.0f / DD);
    float y  = d * rsqrtf(var + 1e-5f) * lng[t] + lnb[t];
    g_y[(long long)row * DD + t] = geluf(y);
}

// ---------------- K7: gather epilogue (HBM-write-bound) ----------------
__global__ void gather_kernel(const int* __restrict__ labels, float4* __restrict__ out) {
    long long idx = (long long)blockIdx.x * blockDim.x + threadIdx.x; // one float4 each
    const long long total = (long long)BB * NN * (DD / 4);
    if (idx >= total) return;
    int       c4 = (int)(idx & (DD / 4 - 1));
    long long pt = idx >> 6;                 // b*N + n
    int       b  = (int)(pt / NN);
    int       lab = __ldg(labels + pt) & (SS - 1); // broadcast within warp, in-bounds
    const float4* row = (const float4*)(g_a4 + ((long long)(b * SS + lab)) * DD);
    float4 v = __ldg(row + c4);              // ~1MB table -> L2 resident
    __stcs(out + idx, v);                    // streaming store, don't pollute L2
}

// ---------------- launch ----------------
extern "C" void kernel_launch(void* const* d_in, const int* in_sizes, int n_in,
                              void* d_out, int out_size) {
    const float* coords = (const float*)d_in[0];
    // d_in[1] = features (unused), d_in[3] = num_superpoints (unused, S fixed at 128)
    const int*   labels = (const int*)d_in[2];   // JAX x64 disabled -> int32
    const float* W1 = (const float*)d_in[4];
    const float* b1 = (const float*)d_in[5];
    const float* W2 = (const float*)d_in[6];
    const float* b2 = (const float*)d_in[7];
    const float* W3 = (const float*)d_in[8];
    const float* b3 = (const float*)d_in[9];
    const float* lng = (const float*)d_in[10];
    const float* lnb = (const float*)d_in[11];
    const float* W4 = (const float*)d_in[12];
    const float* b4 = (const float*)d_in[13];

    zero_kernel<<<12, 256>>>();
    accum_kernel<<<dim3((NN + PTS_PER_BLK - 1) / PTS_PER_BLK, BB), 256>>>(coords, labels);
    relh1_kernel<<<BB, SS>>>(W1, b1);
    gemm_kernel<HID, 0><<<dim3(DD / 32, BB), 256>>>(W2, b2);
    gemm_kernel<DD, 1><<<dim3(DD / 32, BB), 256>>>(W3, b3);
    ln_gelu_kernel<<<BB * SS, DD>>>(lng, lnb);
    gemm_kernel<DD, 2><<<dim3(DD / 32, BB), 256>>>(W4, b4);

    long long total4 = (long long)BB * NN * (DD / 4);
    int blocks = (int)((total4 + 255) / 256);
    gather_kernel<<<blocks, 256>>>(labels, (float4*)d_out);
}

// round 3
// speedup vs baseline: 2.1696x; 2.1696x over previous
#include <cuda_runtime.h>
#include <math.h>

#define BB   8
#define NN   40000
#define DD   256
#define SS   128
#define HID  64
#define RPB  4      // rows per block in fused middle kernel

// ---------------- device scratch (no allocations allowed) ----------------
__device__ long long g_isum[BB * SS * 3];   // fixed-point coordinate sums (scale 2^32)
__device__ int       g_icnt[BB * SS];       // exact counts
__device__ float     g_a4  [BB * SS * DD];  // final per-superpoint table (masked)

__device__ __forceinline__ float geluf(float x) { return x * normcdff(x); }

// ---------------- K0: zero the integer accumulators ----------------
__global__ void zero_kernel() {
    int i = blockIdx.x * blockDim.x + threadIdx.x;
    if (i < BB * SS)     g_icnt[i] = 0;
    if (i < BB * SS * 3) g_isum[i] = 0;
}

// ---------------- K1: segment accumulation (shared-privatized, integer atomics) ----------------
#define PTS_PER_BLK 2048
__global__ void accum_kernel(const float* __restrict__ coords,
                             const int* __restrict__ labels) {
    __shared__ int       s_cnt[SS];
    __shared__ long long s_sum[SS * 3];
    int b    = blockIdx.y;
    int base = blockIdx.x * PTS_PER_BLK;

    for (int i = threadIdx.x; i < SS; i += blockDim.x) {
        s_cnt[i] = 0;
        s_sum[i * 3 + 0] = 0; s_sum[i * 3 + 1] = 0; s_sum[i * 3 + 2] = 0;
    }
    __syncthreads();

    const double SCALE = 4294967296.0; // 2^32 fixed point -> deterministic & exact enough
    for (int i = threadIdx.x; i < PTS_PER_BLK; i += blockDim.x) {
        int n = base + i;
        if (n < NN) {
            long long pt = (long long)b * NN + n;
            int lab = labels[pt] & (SS - 1);
            const float* c = coords + pt * 3;
            atomicAdd(&s_cnt[lab], 1);
            atomicAdd((unsigned long long*)&s_sum[lab * 3 + 0],
                      (unsigned long long)llrint((double)c[0] * SCALE));
            atomicAdd((unsigned long long*)&s_sum[lab * 3 + 1],
                      (unsigned long long)llrint((double)c[1] * SCALE));
            atomicAdd((unsigned long long*)&s_sum[lab * 3 + 2],
                      (unsigned long long)llrint((double)c[2] * SCALE));
        }
    }
    __syncthreads();

    for (int i = threadIdx.x; i < SS; i += blockDim.x) {
        if (s_cnt[i]) {
            atomicAdd(&g_icnt[b * SS + i], s_cnt[i]);
            atomicAdd((unsigned long long*)&g_isum[(b * SS + i) * 3 + 0],
                      (unsigned long long)s_sum[i * 3 + 0]);
            atomicAdd((unsigned long long*)&g_isum[(b * SS + i) * 3 + 1],
                      (unsigned long long)s_sum[i * 3 + 1]);
            atomicAdd((unsigned long long*)&g_isum[(b * SS + i) * 3 + 2],
                      (unsigned long long)s_sum[i * 3 + 2]);
        }
    }
}

// ---------------- K2: fully fused middle ----------------
// Per block: batch b, rows [r0, r0+4). Computes centers -> rel -> h1 -> h2 -> a3
// -> layernorm+gelu -> a4 (masked) entirely on-chip; writes only g_a4.
__global__ __launch_bounds__(256) void middle_kernel(
    const float* __restrict__ W1, const float* __restrict__ b1,
    const float* __restrict__ W2, const float* __restrict__ b2,
    const float* __restrict__ W3, const float* __restrict__ b3,
    const float* __restrict__ lng, const float* __restrict__ lnb,
    const float* __restrict__ W4, const float* __restrict__ b4)
{
    int b   = blockIdx.y;
    int r0  = blockIdx.x * RPB;
    int tid = threadIdx.x;
    int lane = tid & 31, w = tid >> 5;

    __shared__ float cx[SS], cy[SS], cz[SS], vm[SS];
    __shared__ float relS[RPB][4];
    __shared__ float maskS[RPB];
    __shared__ float h1s[RPB][HID];
    __shared__ float h2s[RPB][DD];
    __shared__ float ys [RPB][DD];
    __shared__ float red[8 * RPB];
    __shared__ float s_nv;

    // ---- centers for ALL superpoints of this batch ----
    if (tid < SS) {
        int   cnt  = g_icnt[b * SS + tid];
        float cf   = (float)cnt;
        float dc   = fmaxf(cf, 1.0f);
        const double INV = 1.0 / 4294967296.0;
        cx[tid] = (float)((double)g_isum[(b * SS + tid) * 3 + 0] * INV) / dc;
        cy[tid] = (float)((double)g_isum[(b * SS + tid) * 3 + 1] * INV) / dc;
        cz[tid] = (float)((double)g_isum[(b * SS + tid) * 3 + 2] * INV) / dc;
        vm[tid] = (cf >= 2.0f) ? 1.0f : 0.0f;
    }
    __syncthreads();
    if (tid == 0) {
        float t = 0.f;
        #pragma unroll 8
        for (int i = 0; i < SS; i++) t += vm[i];
        s_nv = t;
    }
    __syncthreads();
    float nv    = s_nv;
    float denom = fmaxf(nv, 1.0f);

    // ---- rel features: warp r (0..3) handles row r0+r ----
    if (w < RPB) {
        int s = r0 + w;
        float xs = cx[s], ysv = cy[s], zs = cz[s];
        float msum = 0.f, mind = INFINITY, fcnt = 0.f;
        #pragma unroll
        for (int t = lane; t < SS; t += 32) {
            float dx = xs - cx[t], dy = ysv - cy[t], dz = zs - cz[t];
            float d2 = dx * dx + dy * dy + dz * dz;
            float dist = (d2 > 0.f) ? sqrtf(d2) : 0.f;
            float v = vm[t];
            msum += dist * v;
            if (v > 0.f) mind = fminf(mind, dist);
            fcnt += (zs > cz[t] ? 1.0f : 0.0f) * v;
        }
        #pragma unroll
        for (int o = 16; o > 0; o >>= 1) {
            msum += __shfl_xor_sync(0xffffffffu, msum, o);
            mind  = fminf(mind, __shfl_xor_sync(0xffffffffu, mind, o));
            fcnt += __shfl_xor_sync(0xffffffffu, fcnt, o);
        }
        if (lane == 0) {
            relS[w][0] = msum / denom;
            relS[w][1] = mind;
            relS[w][2] = zs;
            relS[w][3] = fcnt / denom;
            maskS[w]   = vm[s] * ((nv >= 2.0f) ? 1.0f : 0.0f);
        }
    }
    __syncthreads();

    // ---- h1 = gelu(rel @ W1 + b1): tid -> (r = tid>>6, j = tid&63) ----
    {
        int r = tid >> 6, j = tid & 63;
        float a = b1[j]
                + relS[r][0] * W1[0 * HID + j]
                + relS[r][1] * W1[1 * HID + j]
                + relS[r][2] * W1[2 * HID + j]
                + relS[r][3] * W1[3 * HID + j];
        h1s[r][j] = geluf(a);
    }
    __syncthreads();

    int c = tid;  // output column, 0..255

    // ---- stage A: h2 = h1 @ W2 + b2  (K=64) ----
    {
        float a0 = 0.f, a1 = 0.f, a2 = 0.f, a3 = 0.f;
        #pragma unroll 8
        for (int k = 0; k < HID; k++) {
            float wv = __ldg(W2 + k * DD + c);
            a0 += h1s[0][k] * wv; a1 += h1s[1][k] * wv;
            a2 += h1s[2][k] * wv; a3 += h1s[3][k] * wv;
        }
        float bv = b2[c];
        h2s[0][c] = a0 + bv; h2s[1][c] = a1 + bv;
        h2s[2][c] = a2 + bv; h2s[3][c] = a3 + bv;
    }
    __syncthreads();

    // ---- stage B: a3 = h2 @ W3 + b3  (K=256) -> registers ----
    float v0, v1, v2, v3;
    {
        float a0 = 0.f, a1 = 0.f, a2 = 0.f, a3 = 0.f;
        #pragma unroll 8
        for (int k = 0; k < DD; k++) {
            float wv = __ldg(W3 + k * DD + c);
            a0 += h2s[0][k] * wv; a1 += h2s[1][k] * wv;
            a2 += h2s[2][k] * wv; a3 += h2s[3][k] * wv;
        }
        float bv = b3[c];
        v0 = a0 + bv; v1 = a1 + bv; v2 = a2 + bv; v3 = a3 + bv;
    }

    // ---- layernorm (per row over 256 cols) + gelu ----
    // round 1: mean
    {
        float s0 = v0, s1 = v1, s2 = v2, s3 = v3;
        #pragma unroll
        for (int o = 16; o > 0; o >>= 1) {
            s0 += __shfl_xor_sync(0xffffffffu, s0, o);
            s1 += __shfl_xor_sync(0xffffffffu, s1, o);
            s2 += __shfl_xor_sync(0xffffffffu, s2, o);
            s3 += __shfl_xor_sync(0xffffffffu, s3, o);
        }
        if (lane == 0) { red[w*4+0]=s0; red[w*4+1]=s1; red[w*4+2]=s2; red[w*4+3]=s3; }
    }
    __syncthreads();
    float m0=0,m1=0,m2=0,m3=0;
    #pragma unroll
    for (int i = 0; i < 8; i++) { m0+=red[i*4+0]; m1+=red[i*4+1]; m2+=red[i*4+2]; m3+=red[i*4+3]; }
    m0 *= (1.0f/DD); m1 *= (1.0f/DD); m2 *= (1.0f/DD); m3 *= (1.0f/DD);
    __syncthreads();
    float d0 = v0-m0, d1 = v1-m1, d2 = v2-m2, d3 = v3-m3;
    // round 2: variance
    {
        float s0 = d0*d0, s1 = d1*d1, s2 = d2*d2, s3 = d3*d3;
        #pragma unroll
        for (int o = 16; o > 0; o >>= 1) {
            s0 += __shfl_xor_sync(0xffffffffu, s0, o);
            s1 += __shfl_xor_sync(0xffffffffu, s1, o);
            s2 += __shfl_xor_sync(0xffffffffu, s2, o);
            s3 += __shfl_xor_sync(0xffffffffu, s3, o);
        }
        if (lane == 0) { red[w*4+0]=s0; red[w*4+1]=s1; red[w*4+2]=s2; red[w*4+3]=s3; }
    }
    __syncthreads();
    float q0=0,q1=0,q2=0,q3=0;
    #pragma unroll
    for (int i = 0; i < 8; i++) { q0+=red[i*4+0]; q1+=red[i*4+1]; q2+=red[i*4+2]; q3+=red[i*4+3]; }
    float g = lng[c], bb = lnb[c];
    ys[0][c] = geluf(d0 * rsqrtf(q0*(1.0f/DD) + 1e-5f) * g + bb);
    ys[1][c] = geluf(d1 * rsqrtf(q1*(1.0f/DD) + 1e-5f) * g + bb);
    ys[2][c] = geluf(d2 * rsqrtf(q2*(1.0f/DD) + 1e-5f) * g + bb);
    ys[3][c] = geluf(d3 * rsqrtf(q3*(1.0f/DD) + 1e-5f) * g + bb);
    __syncthreads();

    // ---- stage C: a4 = (y @ W4 + b4) * mask -> g_a4 ----
    {
        float a0 = 0.f, a1 = 0.f, a2 = 0.f, a3 = 0.f;
        #pragma unroll 8
        for (int k = 0; k < DD; k++) {
            float wv = __ldg(W4 + k * DD + c);
            a0 += ys[0][k] * wv; a1 += ys[1][k] * wv;
            a2 += ys[2][k] * wv; a3 += ys[3][k] * wv;
        }
        float bv = b4[c];
        float* out = g_a4 + ((long long)b * SS + r0) * DD + c;
        out[0 * DD] = (a0 + bv) * maskS[0];
        out[1 * DD] = (a1 + bv) * maskS[1];
        out[2 * DD] = (a2 + bv) * maskS[2];
        out[3 * DD] = (a3 + bv) * maskS[3];
    }
}

// ---------------- K3: gather epilogue (HBM-write-bound roofline) ----------------
// Each thread writes 2 float4s of one point's row; one label per warp (broadcast).
__global__ void gather_kernel(const int* __restrict__ labels, float4* __restrict__ out) {
    int b   = blockIdx.y;
    int idx = blockIdx.x * 256 + threadIdx.x;   // 0 .. NN*32-1 (exact, 5000 blocks)
    int pt  = idx >> 5;                         // point within batch
    int c4  = idx & 31;
    int lab = __ldg(labels + b * NN + pt) & (SS - 1);
    const float4* row = (const float4*)(g_a4 + (long long)(b * SS + lab) * DD);
    float4 u0 = __ldg(row + c4);
    float4 u1 = __ldg(row + c4 + 32);
    float4* o = out + ((long long)b * NN + pt) * (DD / 4);
    __stcs(o + c4,      u0);
    __stcs(o + c4 + 32, u1);
}

// ---------------- launch ----------------
extern "C" void kernel_launch(void* const* d_in, const int* in_sizes, int n_in,
                              void* d_out, int out_size) {
    const float* coords = (const float*)d_in[0];
    // d_in[1] = features (unused), d_in[3] = num_superpoints (compile-time 128)
    const int*   labels = (const int*)d_in[2];
    const float* W1  = (const float*)d_in[4];
    const float* b1  = (const float*)d_in[5];
    const float* W2  = (const float*)d_in[6];
    const float* b2  = (const float*)d_in[7];
    const float* W3  = (const float*)d_in[8];
    const float* b3  = (const float*)d_in[9];
    const float* lng = (const float*)d_in[10];
    const float* lnb = (const float*)d_in[11];
    const float* W4  = (const float*)d_in[12];
    const float* b4  = (const float*)d_in[13];

    zero_kernel<<<12, 256>>>();
    accum_kernel<<<dim3((NN + PTS_PER_BLK - 1) / PTS_PER_BLK, BB), 256>>>(coords, labels);
    middle_kernel<<<dim3(SS / RPB, BB), 256>>>(W1, b1, W2, b2, W3, b3, lng, lnb, W4, b4);
    gather_kernel<<<dim3((NN * 32) / 256, BB), 256>>>(labels, (float4*)d_out);
}